// round 11
// baseline (speedup 1.0000x reference)
#include <cuda_runtime.h>
#include <cuda_bf16.h>
#include <math.h>
#include <stdint.h>

#define BB 4
#define HH 16
#define SSEQ 1024
#define DKD 64
#define TQ 128
#define NT 512
#define NEGV (-1.0e9f)
#define PADB 144

#define KSTG   36864                       // one K stage (hi 18432 + lo 18432)
#define OFF_STG (3 * KSTG)                 // 110592: staging; transient Q lives here too
#define STRW   272                         // staging row stride (bytes)
#define WSTG   (16 * STRW)                 // 4352 per warp
#define OFF_RED (OFF_STG + 16 * WSTG)      // 180224
#define SMEM_TOTAL (OFF_RED + (256 + 128) * 4)   // 181760 -> occ 1

#define NELEM (BB * HH * SSEQ * DKD)
#define NMASK (BB * SSEQ * SSEQ)
#define CVT_BLOCKS ((2 * NELEM / 4) / 256)
#define MSK_BLOCKS ((NMASK / 16) / 256)

__device__ __nv_bfloat16 gQhi[NELEM];
__device__ __nv_bfloat16 gQlo[NELEM];
__device__ __nv_bfloat16 gKhi[NELEM];
__device__ __nv_bfloat16 gKlo[NELEM];
__device__ __align__(16) uint8_t gMB[NMASK];

__device__ __forceinline__ uint32_t smem_u32(const void* p) {
    uint32_t a;
    asm("{ .reg .u64 t; cvta.to.shared.u64 t, %1; cvt.u32.u64 %0, t; }" : "=r"(a) : "l"(p));
    return a;
}
__device__ __forceinline__ uint32_t pack_bf2(__nv_bfloat16 a, __nv_bfloat16 b) {
    return (uint32_t)__bfloat16_as_ushort(a) | ((uint32_t)__bfloat16_as_ushort(b) << 16);
}
__device__ __forceinline__ void mma_bf16(float* d,
                                         uint32_t a0, uint32_t a1, uint32_t a2, uint32_t a3,
                                         uint32_t b0, uint32_t b1) {
    asm volatile(
        "mma.sync.aligned.m16n8k16.row.col.f32.bf16.bf16.f32 "
        "{%0,%1,%2,%3}, {%4,%5,%6,%7}, {%8,%9}, {%0,%1,%2,%3};"
        : "+f"(d[0]), "+f"(d[1]), "+f"(d[2]), "+f"(d[3])
        : "r"(a0), "r"(a1), "r"(a2), "r"(a3), "r"(b0), "r"(b1));
}
#define LDSM4(r0, r1, r2, r3, a) \
    asm volatile("ldmatrix.sync.aligned.m8n8.x4.shared.b16 {%0,%1,%2,%3}, [%4];" \
                 : "=r"(r0), "=r"(r1), "=r"(r2), "=r"(r3) : "r"(a))
#define CP16(dst, src) \
    asm volatile("cp.async.cg.shared.global [%0], [%1], 16;" :: "r"(dst), "l"(src) : "memory")

// ---- combined pre-pass: bf16 hi/lo conversion + mask byte-packing ----
__global__ void __launch_bounds__(256, 8)
prep_kernel(const float* __restrict__ Q, const float* __restrict__ K,
            const int* __restrict__ M)
{
    if (blockIdx.x < CVT_BLOCKS) {
        size_t i = (size_t)blockIdx.x * 256 + threadIdx.x;
        bool isQ = i < (NELEM / 4);
        size_t j = isQ ? i : i - (NELEM / 4);
        float4 v = reinterpret_cast<const float4*>(isQ ? Q : K)[j];
        if (isQ) { v.x *= 0.125f; v.y *= 0.125f; v.z *= 0.125f; v.w *= 0.125f; }
        __nv_bfloat16 bx = __float2bfloat16_rn(v.x), by = __float2bfloat16_rn(v.y);
        __nv_bfloat16 bz = __float2bfloat16_rn(v.z), bw = __float2bfloat16_rn(v.w);
        uint2 hi = make_uint2(pack_bf2(bx, by), pack_bf2(bz, bw));
        uint2 lo = make_uint2(
            pack_bf2(__float2bfloat16_rn(v.x - __bfloat162float(bx)),
                     __float2bfloat16_rn(v.y - __bfloat162float(by))),
            pack_bf2(__float2bfloat16_rn(v.z - __bfloat162float(bz)),
                     __float2bfloat16_rn(v.w - __bfloat162float(bw))));
        if (isQ) { reinterpret_cast<uint2*>(gQhi)[j] = hi; reinterpret_cast<uint2*>(gQlo)[j] = lo; }
        else     { reinterpret_cast<uint2*>(gKhi)[j] = hi; reinterpret_cast<uint2*>(gKlo)[j] = lo; }
    } else {
        int t = (blockIdx.x - CVT_BLOCKS) * 256 + threadIdx.x;
        int tile = t >> 3;
        int w = t & 7;
        int half = w >> 2, e = w & 3;
        const int* src = M + (size_t)tile * 128 + half * 64 + 2 * e;
        uint32_t words[4];
        #pragma unroll
        for (int p = 0; p < 4; p++) {
            int2 v0 = *reinterpret_cast<const int2*>(src + (2 * p) * 8);
            int2 v1 = *reinterpret_cast<const int2*>(src + (2 * p + 1) * 8);
            words[p] = (v0.x ? 1u : 0u) | (v0.y ? 0x100u : 0u)
                     | (v1.x ? 0x10000u : 0u) | (v1.y ? 0x1000000u : 0u);
        }
        *reinterpret_cast<uint4*>(gMB + (size_t)tile * 128 + w * 16) =
            make_uint4(words[0], words[1], words[2], words[3]);
    }
}

__global__ void __launch_bounds__(NT, 1)
mha_fused(float* __restrict__ attn, float* __restrict__ scores)
{
    extern __shared__ char sm[];
    float* sred = (float*)(sm + OFF_RED);   // [256]
    float* sinv = sred + 256;               // [128]

    const int tid  = threadIdx.x;
    const int lane = tid & 31;
    const int wid  = tid >> 5;
    const int wq   = wid >> 1;              // 0..7
    const int wk   = wid & 1;               // 0..1
    const int qt = blockIdx.x, h = blockIdx.y, b = blockIdx.z;
    const int q0 = qt * TQ;

    const size_t qbase = ((size_t)(b * HH + h) * SSEQ + q0) * DKD;
    const size_t kbase = (size_t)(b * HH + h) * SSEQ * DKD;
    const uint8_t* Mb = gMB + ((size_t)b * SSEQ + q0) * SSEQ;
    float* Sp = scores + ((size_t)(b * HH + h) * SSEQ + q0) * SSEQ;
    float* Ap = attn   + ((size_t)(b * HH + h) * SSEQ + q0) * SSEQ;

    const uint32_t sbase = smem_u32(sm);
    const uint32_t sqb   = sbase + OFF_STG;          // transient Q (overlaps staging)
    const uint32_t sstg  = sbase + OFF_STG + wid * WSTG;

    // ---- prologue: Q (hi+lo) -> staging region; K tiles 0,1 -> stages 0,1 ----
    #pragma unroll
    for (int i = 0; i < 4; i++) {
        int idx = tid + i * NT;
        int half = idx >> 10, r = (idx >> 3) & 127, c = idx & 7;
        CP16(sqb + (uint32_t)(half * 18432 + r * PADB + c * 16),
             (half ? gQlo : gQhi) + qbase + (size_t)r * DKD + c * 8);
    }
    #pragma unroll
    for (int i = 0; i < 4; i++) {
        int idx = tid + i * NT;
        int half = idx >> 10, r = (idx >> 3) & 127, c = idx & 7;
        CP16(sbase + (uint32_t)(half * 18432 + r * PADB + c * 16),
             (half ? gKlo : gKhi) + kbase + (size_t)r * DKD + c * 8);
    }
    asm volatile("cp.async.commit_group;" ::: "memory");   // g0: Q + K0
    #pragma unroll
    for (int i = 0; i < 4; i++) {
        int idx = tid + i * NT;
        int half = idx >> 10, r = (idx >> 3) & 127, c = idx & 7;
        CP16(sbase + (uint32_t)(KSTG + half * 18432 + r * PADB + c * 16),
             (half ? gKlo : gKhi) + kbase + (size_t)(128 + r) * DKD + c * 8);
    }
    asm volatile("cp.async.commit_group;" ::: "memory");   // g1: K1

    // ---- wait for Q (g0), hoist A fragments into registers ----
    asm volatile("cp.async.wait_group 1;" ::: "memory");
    __syncthreads();
    uint32_t ah[4][4], al[4][4];
    {
        const uint32_t aHi = sqb + (uint32_t)((wq * 16 + (lane & 15)) * PADB + (lane >> 4) * 16);
        const uint32_t aLo = aHi + 18432;
        #pragma unroll
        for (int s = 0; s < 4; s++) {
            LDSM4(ah[s][0], ah[s][1], ah[s][2], ah[s][3], aHi + s * 32);
            LDSM4(al[s][0], al[s][1], al[s][2], al[s][3], aLo + s * 32);
        }
    }

    const int rowB = wk * 64 + (lane & 7) + (lane >> 4) * 8;
    const uint32_t bOff = (uint32_t)(rowB * PADB + ((lane >> 3) & 1) * 16);

    const int r0l = wq * 16 + (lane >> 2);
    const int qq = lane >> 2, ee = lane & 3;
    const uint8_t* mp0 = Mb + (size_t)r0l * SSEQ + wk * 64 + (lane & 3) * 16;
    const uint8_t* mp8 = mp0 + 8 * SSEQ;
    float sumE0 = 0.0f, sumE1 = 0.0f;

    int st = 0;
    for (int t = 0; t < SSEQ / 128; t++) {
        const int kt = t * 128;
        asm volatile("cp.async.wait_group 1;" ::: "memory");
        __syncthreads();   // single barrier: tile t ready; all warps past tile t-1

        const uint32_t bHi = sbase + (uint32_t)(st * KSTG) + bOff;
        const uint32_t bLo = bHi + 18432;

        float acc[8][4];
        #pragma unroll
        for (int n = 0; n < 8; n++)
            #pragma unroll
            for (int j = 0; j < 4; j++) acc[n][j] = 0.0f;

        #pragma unroll
        for (int s = 0; s < 4; s++) {
            #pragma unroll
            for (int p = 0; p < 4; p++) {
                uint32_t bh0, bh1, bh2, bh3, bl0, bl1, bl2, bl3;
                LDSM4(bh0, bh1, bh2, bh3, bHi + (uint32_t)(p * 16 * PADB + s * 32));
                LDSM4(bl0, bl1, bl2, bl3, bLo + (uint32_t)(p * 16 * PADB + s * 32));
                mma_bf16(acc[2 * p],     ah[s][0], ah[s][1], ah[s][2], ah[s][3], bh0, bh1);
                mma_bf16(acc[2 * p],     ah[s][0], ah[s][1], ah[s][2], ah[s][3], bl0, bl1);
                mma_bf16(acc[2 * p],     al[s][0], al[s][1], al[s][2], al[s][3], bh0, bh1);
                mma_bf16(acc[2 * p + 1], ah[s][0], ah[s][1], ah[s][2], ah[s][3], bh2, bh3);
                mma_bf16(acc[2 * p + 1], ah[s][0], ah[s][1], ah[s][2], ah[s][3], bl2, bl3);
                mma_bf16(acc[2 * p + 1], al[s][0], al[s][1], al[s][2], al[s][3], bh2, bh3);
            }
        }

        // ---- prefetch tile t+2 into stage (st+2)%3 (consumed two tiles ago) ----
        int sp = st + 2; if (sp >= 3) sp -= 3;
        if (t + 2 < SSEQ / 128) {
            #pragma unroll
            for (int i = 0; i < 4; i++) {
                int idx = tid + i * NT;
                int half = idx >> 10, r = (idx >> 3) & 127, c = idx & 7;
                CP16(sbase + (uint32_t)(sp * KSTG + half * 18432 + r * PADB + c * 16),
                     (half ? gKlo : gKhi) + kbase + (size_t)(kt + 256 + r) * DKD + c * 8);
            }
        }
        asm volatile("cp.async.commit_group;" ::: "memory");

        // ---- epilogue: mask, exp sums, stage scores, coalesced STG.128 ----
        uint4 mA = *reinterpret_cast<const uint4*>(mp0 + kt);
        uint4 mB = *reinterpret_cast<const uint4*>(mp8 + kt);
        const uint32_t* wa = reinterpret_cast<const uint32_t*>(&mA);
        const uint32_t* wb = reinterpret_cast<const uint32_t*>(&mB);

        __syncwarp();   // previous tile's staging reads complete
        #pragma unroll
        for (int nt = 0; nt < 8; nt++) {
            uint32_t ma = wa[nt >> 1] >> ((nt & 1) * 16);
            uint32_t mb = wb[nt >> 1] >> ((nt & 1) * 16);
            float s0 = (ma & 0xFFu)   ? acc[nt][0] : NEGV;
            float s1 = (ma & 0xFF00u) ? acc[nt][1] : NEGV;
            float s2 = (mb & 0xFFu)   ? acc[nt][2] : NEGV;
            float s3 = (mb & 0xFF00u) ? acc[nt][3] : NEGV;
            sumE0 += __expf(s0) + __expf(s1);
            sumE1 += __expf(s2) + __expf(s3);
            *reinterpret_cast<float2*>(sm + (sstg - sbase) + qq * STRW + nt * 32 + ee * 8) =
                make_float2(s0, s1);
            *reinterpret_cast<float2*>(sm + (sstg - sbase) + (8 + qq) * STRW + nt * 32 + ee * 8) =
                make_float2(s2, s3);
        }
        __syncwarp();
        #pragma unroll
        for (int j = 0; j < 8; j++) {
            int rho = 2 * j + (lane >> 4);
            int p   = lane & 15;
            float4 v = *reinterpret_cast<const float4*>(sm + (sstg - sbase) + rho * STRW + p * 16);
            *reinterpret_cast<float4*>(Sp + (size_t)(wq * 16 + rho) * SSEQ + kt + wk * 64 + p * 4) = v;
        }

        st++; if (st == 3) st = 0;
    }

    // ---- row-sum reduce ----
    sumE0 += __shfl_xor_sync(0xFFFFFFFFu, sumE0, 1);
    sumE0 += __shfl_xor_sync(0xFFFFFFFFu, sumE0, 2);
    sumE1 += __shfl_xor_sync(0xFFFFFFFFu, sumE1, 1);
    sumE1 += __shfl_xor_sync(0xFFFFFFFFu, sumE1, 2);
    if ((lane & 3) == 0) {
        sred[wk * 128 + r0l]     = sumE0;
        sred[wk * 128 + r0l + 8] = sumE1;
    }
    __syncthreads();
    if (tid < 128) sinv[tid] = 1.0f / (sred[tid] + sred[128 + tid]);
    __syncthreads();

    // ---- fused attn pass: re-read scores (L2-hot), normalize ----
    #pragma unroll 8
    for (int i = 0; i < 64; i++) {
        int idx = tid + i * NT;
        float inv = sinv[idx >> 8];
        float4 s = reinterpret_cast<const float4*>(Sp)[idx];
        float4 a;
        a.x = __expf(s.x) * inv;
        a.y = __expf(s.y) * inv;
        a.z = __expf(s.z) * inv;
        a.w = __expf(s.w) * inv;
        reinterpret_cast<float4*>(Ap)[idx] = a;
    }
}

extern "C" void kernel_launch(void* const* d_in, const int* in_sizes, int n_in,
                              void* d_out, int out_size)
{
    const float* Q = (const float*)d_in[0];
    const float* K = (const float*)d_in[1];
    const int*   M = (const int*)d_in[3];    // d_in[2] = value, unused by outputs

    float* attn   = (float*)d_out;
    float* scores = (float*)d_out + (size_t)BB * HH * SSEQ * SSEQ;

    prep_kernel<<<CVT_BLOCKS + MSK_BLOCKS, 256>>>(Q, K, M);

    cudaFuncSetAttribute(mha_fused, cudaFuncAttributeMaxDynamicSharedMemorySize, SMEM_TOTAL);
    dim3 grid(SSEQ / TQ, HH, BB);            // (8,16,4) = 512 CTAs
    mha_fused<<<grid, NT, SMEM_TOTAL>>>(attn, scores);
}

// round 12
// speedup vs baseline: 1.2934x; 1.2934x over previous
#include <cuda_runtime.h>
#include <cuda_bf16.h>
#include <math.h>
#include <stdint.h>

#define BB 4
#define HH 16
#define SSEQ 1024
#define DKD 64
#define TQ 128
#define NT 512
#define NEGV (-1.0e9f)
#define PADB 144

#define OFF_QHI 0
#define OFF_QLO 18432
#define OFF_K   36864
#define KSTAGE  36864
#define OFF_RED (OFF_K + 2 * KSTAGE)              // 110592
#define SMEM_TOTAL (OFF_RED + (256 + 128) * 4)    // 112128 -> 2 CTAs/SM

#define NELEM (BB * HH * SSEQ * DKD)
#define NMASK (BB * SSEQ * SSEQ)
#define CVT_BLOCKS ((2 * NELEM / 4) / 256)
#define MSK_BLOCKS ((NMASK / 16) / 256)

__device__ __nv_bfloat16 gQhi[NELEM];
__device__ __nv_bfloat16 gQlo[NELEM];
__device__ __nv_bfloat16 gKhi[NELEM];
__device__ __nv_bfloat16 gKlo[NELEM];
__device__ __align__(16) uint8_t gMB[NMASK];

__device__ __forceinline__ uint32_t smem_u32(const void* p) {
    uint32_t a;
    asm("{ .reg .u64 t; cvta.to.shared.u64 t, %1; cvt.u32.u64 %0, t; }" : "=r"(a) : "l"(p));
    return a;
}
__device__ __forceinline__ uint32_t pack_bf2(__nv_bfloat16 a, __nv_bfloat16 b) {
    return (uint32_t)__bfloat16_as_ushort(a) | ((uint32_t)__bfloat16_as_ushort(b) << 16);
}
__device__ __forceinline__ void mma_bf16(float* d,
                                         uint32_t a0, uint32_t a1, uint32_t a2, uint32_t a3,
                                         uint32_t b0, uint32_t b1) {
    asm volatile(
        "mma.sync.aligned.m16n8k16.row.col.f32.bf16.bf16.f32 "
        "{%0,%1,%2,%3}, {%4,%5,%6,%7}, {%8,%9}, {%0,%1,%2,%3};"
        : "+f"(d[0]), "+f"(d[1]), "+f"(d[2]), "+f"(d[3])
        : "r"(a0), "r"(a1), "r"(a2), "r"(a3), "r"(b0), "r"(b1));
}
#define LDSM4(r0, r1, r2, r3, a) \
    asm volatile("ldmatrix.sync.aligned.m8n8.x4.shared.b16 {%0,%1,%2,%3}, [%4];" \
                 : "=r"(r0), "=r"(r1), "=r"(r2), "=r"(r3) : "r"(a))
#define CP16(dst, src) \
    asm volatile("cp.async.cg.shared.global [%0], [%1], 16;" :: "r"(dst), "l"(src) : "memory")

// ---- combined pre-pass: bf16 hi/lo conversion + mask byte-packing ----
__global__ void __launch_bounds__(256, 8)
prep_kernel(const float* __restrict__ Q, const float* __restrict__ K,
            const int* __restrict__ M)
{
    if (blockIdx.x < CVT_BLOCKS) {
        size_t i = (size_t)blockIdx.x * 256 + threadIdx.x;
        bool isQ = i < (NELEM / 4);
        size_t j = isQ ? i : i - (NELEM / 4);
        float4 v = reinterpret_cast<const float4*>(isQ ? Q : K)[j];
        if (isQ) { v.x *= 0.125f; v.y *= 0.125f; v.z *= 0.125f; v.w *= 0.125f; }
        __nv_bfloat16 bx = __float2bfloat16_rn(v.x), by = __float2bfloat16_rn(v.y);
        __nv_bfloat16 bz = __float2bfloat16_rn(v.z), bw = __float2bfloat16_rn(v.w);
        uint2 hi = make_uint2(pack_bf2(bx, by), pack_bf2(bz, bw));
        uint2 lo = make_uint2(
            pack_bf2(__float2bfloat16_rn(v.x - __bfloat162float(bx)),
                     __float2bfloat16_rn(v.y - __bfloat162float(by))),
            pack_bf2(__float2bfloat16_rn(v.z - __bfloat162float(bz)),
                     __float2bfloat16_rn(v.w - __bfloat162float(bw))));
        if (isQ) { reinterpret_cast<uint2*>(gQhi)[j] = hi; reinterpret_cast<uint2*>(gQlo)[j] = lo; }
        else     { reinterpret_cast<uint2*>(gKhi)[j] = hi; reinterpret_cast<uint2*>(gKlo)[j] = lo; }
    } else {
        int t = (blockIdx.x - CVT_BLOCKS) * 256 + threadIdx.x;
        int tile = t >> 3;
        int w = t & 7;
        int half = w >> 2, e = w & 3;
        const int* src = M + (size_t)tile * 128 + half * 64 + 2 * e;
        uint32_t words[4];
        #pragma unroll
        for (int p = 0; p < 4; p++) {
            int2 v0 = *reinterpret_cast<const int2*>(src + (2 * p) * 8);
            int2 v1 = *reinterpret_cast<const int2*>(src + (2 * p + 1) * 8);
            words[p] = (v0.x ? 1u : 0u) | (v0.y ? 0x100u : 0u)
                     | (v1.x ? 0x10000u : 0u) | (v1.y ? 0x1000000u : 0u);
        }
        *reinterpret_cast<uint4*>(gMB + (size_t)tile * 128 + w * 16) =
            make_uint4(words[0], words[1], words[2], words[3]);
    }
}

__global__ void __launch_bounds__(NT, 2)
mha_fused(float* __restrict__ attn, float* __restrict__ scores)
{
    extern __shared__ char sm[];
    float* sred = (float*)(sm + OFF_RED);   // [256]
    float* sinv = sred + 256;               // [128]

    const int tid  = threadIdx.x;
    const int lane = tid & 31;
    const int wid  = tid >> 5;              // 0..15
    const int wq   = wid >> 1;              // 0..7
    const int wk   = wid & 1;               // 0..1
    const int qt = blockIdx.x, h = blockIdx.y, b = blockIdx.z;
    const int q0 = qt * TQ;

    const size_t qbase = ((size_t)(b * HH + h) * SSEQ + q0) * DKD;
    const size_t kbase = (size_t)(b * HH + h) * SSEQ * DKD;
    const uint8_t* Mb = gMB + ((size_t)b * SSEQ + q0) * SSEQ;
    float* Sp = scores + ((size_t)(b * HH + h) * SSEQ + q0) * SSEQ;
    float* Ap = attn   + ((size_t)(b * HH + h) * SSEQ + q0) * SSEQ;

    const uint32_t sq = smem_u32(sm);
    const uint32_t sk = sq + OFF_K;

    // ---- prologue: one group = Q (hi+lo) + K tile 0 -> stage 0 ----
    #pragma unroll
    for (int i = 0; i < 4; i++) {
        int idx = tid + i * NT;
        int half = idx >> 10, r = (idx >> 3) & 127, c = idx & 7;
        CP16(sq + (uint32_t)(half * OFF_QLO + r * PADB + c * 16),
             (half ? gQlo : gQhi) + qbase + (size_t)r * DKD + c * 8);
    }
    #pragma unroll
    for (int i = 0; i < 4; i++) {
        int idx = tid + i * NT;
        int half = idx >> 10, r = (idx >> 3) & 127, c = idx & 7;
        CP16(sk + (uint32_t)(half * 18432 + r * PADB + c * 16),
             (half ? gKlo : gKhi) + kbase + (size_t)r * DKD + c * 8);
    }
    asm volatile("cp.async.commit_group;" ::: "memory");

    const uint32_t aHi = sq + (uint32_t)((wq * 16 + (lane & 15)) * PADB + (lane >> 4) * 16);
    const uint32_t aLo = aHi + OFF_QLO;
    const int rowB = wk * 64 + (lane & 7) + (lane >> 4) * 8;
    const uint32_t bBase = sk + (uint32_t)(rowB * PADB + ((lane >> 3) & 1) * 16);

    const int r0l = wq * 16 + (lane >> 2);
    const uint8_t* mp0 = Mb + (size_t)r0l * SSEQ + wk * 64 + (lane & 3) * 16;
    const uint8_t* mp8 = mp0 + 8 * SSEQ;
    float sumE0 = 0.0f, sumE1 = 0.0f;

    for (int t = 0; t < SSEQ / 128; t++) {
        const int kt = t * 128;
        asm volatile("cp.async.wait_group 0;" ::: "memory");
        __syncthreads();   // tile t resident in stage t&1; stage (t+1)&1 fully consumed

        // ---- prefetch tile t+1 into stage (t+1)&1 (overlaps GEMM + epilogue) ----
        if (t + 1 < SSEQ / 128) {
            #pragma unroll
            for (int i = 0; i < 4; i++) {
                int idx = tid + i * NT;
                int half = idx >> 10, r = (idx >> 3) & 127, c = idx & 7;
                CP16(sk + (uint32_t)(((t + 1) & 1) * KSTAGE + half * 18432 + r * PADB + c * 16),
                     (half ? gKlo : gKhi) + kbase + (size_t)(kt + 128 + r) * DKD + c * 8);
            }
            asm volatile("cp.async.commit_group;" ::: "memory");
        }

        const uint32_t bHi = bBase + (uint32_t)((t & 1) * KSTAGE);
        const uint32_t bLo = bHi + 18432;

        float acc[8][4];
        #pragma unroll
        for (int n = 0; n < 8; n++)
            #pragma unroll
            for (int j = 0; j < 4; j++) acc[n][j] = 0.0f;

        #pragma unroll
        for (int s = 0; s < 4; s++) {
            uint32_t ah0, ah1, ah2, ah3, al0, al1, al2, al3;
            LDSM4(ah0, ah1, ah2, ah3, aHi + s * 32);
            LDSM4(al0, al1, al2, al3, aLo + s * 32);
            #pragma unroll
            for (int p = 0; p < 4; p++) {
                uint32_t bh0, bh1, bh2, bh3, bl0, bl1, bl2, bl3;
                LDSM4(bh0, bh1, bh2, bh3, bHi + (uint32_t)(p * 16 * PADB + s * 32));
                LDSM4(bl0, bl1, bl2, bl3, bLo + (uint32_t)(p * 16 * PADB + s * 32));
                mma_bf16(acc[2 * p],     ah0, ah1, ah2, ah3, bh0, bh1);
                mma_bf16(acc[2 * p],     ah0, ah1, ah2, ah3, bl0, bl1);
                mma_bf16(acc[2 * p],     al0, al1, al2, al3, bh0, bh1);
                mma_bf16(acc[2 * p + 1], ah0, ah1, ah2, ah3, bh2, bh3);
                mma_bf16(acc[2 * p + 1], ah0, ah1, ah2, ah3, bl2, bl3);
                mma_bf16(acc[2 * p + 1], al0, al1, al2, al3, bh2, bh3);
            }
        }

        // ---- epilogue: packed mask, write scores, exp sums ----
        uint4 mA = *reinterpret_cast<const uint4*>(mp0 + kt);
        uint4 mB = *reinterpret_cast<const uint4*>(mp8 + kt);
        const uint32_t* wa = reinterpret_cast<const uint32_t*>(&mA);
        const uint32_t* wb = reinterpret_cast<const uint32_t*>(&mB);
        #pragma unroll
        for (int nt = 0; nt < 8; nt++) {
            uint32_t ma = wa[nt >> 1] >> ((nt & 1) * 16);
            uint32_t mb = wb[nt >> 1] >> ((nt & 1) * 16);
            float s0 = (ma & 0xFFu)   ? acc[nt][0] : NEGV;
            float s1 = (ma & 0xFF00u) ? acc[nt][1] : NEGV;
            float s2 = (mb & 0xFFu)   ? acc[nt][2] : NEGV;
            float s3 = (mb & 0xFF00u) ? acc[nt][3] : NEGV;
            sumE0 += __expf(s0) + __expf(s1);
            sumE1 += __expf(s2) + __expf(s3);
            int kc = kt + wk * 64 + nt * 8 + 2 * (lane & 3);
            *reinterpret_cast<float2*>(Sp + (size_t)r0l * SSEQ + kc)       = make_float2(s0, s1);
            *reinterpret_cast<float2*>(Sp + (size_t)(r0l + 8) * SSEQ + kc) = make_float2(s2, s3);
        }
    }

    // ---- row-sum reduce ----
    sumE0 += __shfl_xor_sync(0xFFFFFFFFu, sumE0, 1);
    sumE0 += __shfl_xor_sync(0xFFFFFFFFu, sumE0, 2);
    sumE1 += __shfl_xor_sync(0xFFFFFFFFu, sumE1, 1);
    sumE1 += __shfl_xor_sync(0xFFFFFFFFu, sumE1, 2);
    if ((lane & 3) == 0) {
        sred[wk * 128 + r0l]     = sumE0;
        sred[wk * 128 + r0l + 8] = sumE1;
    }
    __syncthreads();
    if (tid < 128) sinv[tid] = 1.0f / (sred[tid] + sred[128 + tid]);
    __syncthreads();

    // ---- fused attn pass: re-read scores in REVERSE tile order (L2 recency) ----
    for (int tile = SSEQ / 128 - 1; tile >= 0; tile--) {
        #pragma unroll
        for (int j = 0; j < 8; j++) {
            int row = j * 16 + wid;                     // 0..127
            int idx = row * 256 + tile * 32 + lane;     // float4 index
            float inv = sinv[row];
            float4 s = reinterpret_cast<const float4*>(Sp)[idx];
            float4 a;
            a.x = __expf(s.x) * inv;
            a.y = __expf(s.y) * inv;
            a.z = __expf(s.z) * inv;
            a.w = __expf(s.w) * inv;
            reinterpret_cast<float4*>(Ap)[idx] = a;
        }
    }
}

extern "C" void kernel_launch(void* const* d_in, const int* in_sizes, int n_in,
                              void* d_out, int out_size)
{
    const float* Q = (const float*)d_in[0];
    const float* K = (const float*)d_in[1];
    const int*   M = (const int*)d_in[3];    // d_in[2] = value, unused by outputs

    float* attn   = (float*)d_out;
    float* scores = (float*)d_out + (size_t)BB * HH * SSEQ * SSEQ;

    prep_kernel<<<CVT_BLOCKS + MSK_BLOCKS, 256>>>(Q, K, M);

    cudaFuncSetAttribute(mha_fused, cudaFuncAttributeMaxDynamicSharedMemorySize, SMEM_TOTAL);
    dim3 grid(SSEQ / TQ, HH, BB);            // (8,16,4) = 512 CTAs
    mha_fused<<<grid, NT, SMEM_TOTAL>>>(attn, scores);
}

// round 13
// speedup vs baseline: 1.4998x; 1.1596x over previous
#include <cuda_runtime.h>
#include <cuda_bf16.h>
#include <cuda_fp16.h>
#include <math.h>
#include <stdint.h>

#define BB 4
#define HH 16
#define SSEQ 1024
#define DKD 64
#define TQ 128
#define NT 512
#define NEGV (-1.0e9f)
#define PADB 144

#define KSTAGE  18432                              // one fp16 K tile (128 rows x 144B)
#define OFF_K   18432                              // after Q tile
#define OFF_RED (OFF_K + 2 * KSTAGE)               // 55296
#define SMEM_TOTAL (OFF_RED + (256 + 128) * 4)     // 56832 -> easily 2 CTAs/SM

#define NELEM (BB * HH * SSEQ * DKD)
#define NMASK (BB * SSEQ * SSEQ)
#define CVT_BLOCKS ((2 * NELEM / 4) / 256)
#define MSK_BLOCKS ((NMASK / 16) / 256)

__device__ __half gQh[NELEM];
__device__ __half gKh[NELEM];
__device__ __align__(16) uint8_t gMB[NMASK];

__device__ __forceinline__ uint32_t smem_u32(const void* p) {
    uint32_t a;
    asm("{ .reg .u64 t; cvta.to.shared.u64 t, %1; cvt.u32.u64 %0, t; }" : "=r"(a) : "l"(p));
    return a;
}
__device__ __forceinline__ uint32_t pack_h2(float a, float b) {
    __half2 h = __floats2half2_rn(a, b);
    return *reinterpret_cast<uint32_t*>(&h);
}
__device__ __forceinline__ void mma_f16(float* d,
                                        uint32_t a0, uint32_t a1, uint32_t a2, uint32_t a3,
                                        uint32_t b0, uint32_t b1) {
    asm volatile(
        "mma.sync.aligned.m16n8k16.row.col.f32.f16.f16.f32 "
        "{%0,%1,%2,%3}, {%4,%5,%6,%7}, {%8,%9}, {%0,%1,%2,%3};"
        : "+f"(d[0]), "+f"(d[1]), "+f"(d[2]), "+f"(d[3])
        : "r"(a0), "r"(a1), "r"(a2), "r"(a3), "r"(b0), "r"(b1));
}
#define LDSM4(r0, r1, r2, r3, a) \
    asm volatile("ldmatrix.sync.aligned.m8n8.x4.shared.b16 {%0,%1,%2,%3}, [%4];" \
                 : "=r"(r0), "=r"(r1), "=r"(r2), "=r"(r3) : "r"(a))
#define CP16(dst, src) \
    asm volatile("cp.async.cg.shared.global [%0], [%1], 16;" :: "r"(dst), "l"(src) : "memory")

// ---- combined pre-pass: fp16 conversion (Q pre-scaled) + mask byte-packing ----
__global__ void __launch_bounds__(256, 8)
prep_kernel(const float* __restrict__ Q, const float* __restrict__ K,
            const int* __restrict__ M)
{
    if (blockIdx.x < CVT_BLOCKS) {
        size_t i = (size_t)blockIdx.x * 256 + threadIdx.x;
        bool isQ = i < (NELEM / 4);
        size_t j = isQ ? i : i - (NELEM / 4);
        float4 v = reinterpret_cast<const float4*>(isQ ? Q : K)[j];
        if (isQ) { v.x *= 0.125f; v.y *= 0.125f; v.z *= 0.125f; v.w *= 0.125f; }
        uint2 out = make_uint2(pack_h2(v.x, v.y), pack_h2(v.z, v.w));
        reinterpret_cast<uint2*>(isQ ? gQh : gKh)[j] = out;
    } else {
        int t = (blockIdx.x - CVT_BLOCKS) * 256 + threadIdx.x;
        int tile = t >> 3;
        int w = t & 7;
        int half = w >> 2, e = w & 3;
        const int* src = M + (size_t)tile * 128 + half * 64 + 2 * e;
        uint32_t words[4];
        #pragma unroll
        for (int p = 0; p < 4; p++) {
            int2 v0 = *reinterpret_cast<const int2*>(src + (2 * p) * 8);
            int2 v1 = *reinterpret_cast<const int2*>(src + (2 * p + 1) * 8);
            words[p] = (v0.x ? 1u : 0u) | (v0.y ? 0x100u : 0u)
                     | (v1.x ? 0x10000u : 0u) | (v1.y ? 0x1000000u : 0u);
        }
        *reinterpret_cast<uint4*>(gMB + (size_t)tile * 128 + w * 16) =
            make_uint4(words[0], words[1], words[2], words[3]);
    }
}

__global__ void __launch_bounds__(NT, 2)
mha_fused(float* __restrict__ attn, float* __restrict__ scores)
{
    extern __shared__ char sm[];
    float* sred = (float*)(sm + OFF_RED);   // [256]
    float* sinv = sred + 256;               // [128]

    const int tid  = threadIdx.x;
    const int lane = tid & 31;
    const int wid  = tid >> 5;              // 0..15
    const int wq   = wid >> 1;              // 0..7
    const int wk   = wid & 1;               // 0..1
    const int qt = blockIdx.x, h = blockIdx.y, b = blockIdx.z;
    const int q0 = qt * TQ;

    const size_t qbase = ((size_t)(b * HH + h) * SSEQ + q0) * DKD;
    const size_t kbase = (size_t)(b * HH + h) * SSEQ * DKD;
    const uint8_t* Mb = gMB + ((size_t)b * SSEQ + q0) * SSEQ;
    float* Sp = scores + ((size_t)(b * HH + h) * SSEQ + q0) * SSEQ;
    float* Ap = attn   + ((size_t)(b * HH + h) * SSEQ + q0) * SSEQ;

    const uint32_t sq = smem_u32(sm);
    const uint32_t sk = sq + OFF_K;

    // ---- prologue: one group = Q tile + K tile 0 -> stage 0 ----
    #pragma unroll
    for (int i = 0; i < 2; i++) {           // Q: 1024 x 16B chunks
        int idx = tid + i * NT;
        int r = idx >> 3, c = idx & 7;
        CP16(sq + (uint32_t)(r * PADB + c * 16), gQh + qbase + (size_t)r * DKD + c * 8);
    }
    #pragma unroll
    for (int i = 0; i < 2; i++) {           // K tile 0: 1024 x 16B chunks
        int idx = tid + i * NT;
        int r = idx >> 3, c = idx & 7;
        CP16(sk + (uint32_t)(r * PADB + c * 16), gKh + kbase + (size_t)r * DKD + c * 8);
    }
    asm volatile("cp.async.commit_group;" ::: "memory");

    const uint32_t aHi = sq + (uint32_t)((wq * 16 + (lane & 15)) * PADB + (lane >> 4) * 16);
    const int rowB = wk * 64 + (lane & 7) + (lane >> 4) * 8;
    const uint32_t bBase = sk + (uint32_t)(rowB * PADB + ((lane >> 3) & 1) * 16);

    const int r0l = wq * 16 + (lane >> 2);
    const uint8_t* mp0 = Mb + (size_t)r0l * SSEQ + wk * 64 + (lane & 3) * 16;
    const uint8_t* mp8 = mp0 + 8 * SSEQ;
    float sumE0 = 0.0f, sumE1 = 0.0f;

    for (int t = 0; t < SSEQ / 128; t++) {
        const int kt = t * 128;
        asm volatile("cp.async.wait_group 0;" ::: "memory");
        __syncthreads();   // tile t resident in stage t&1; stage (t+1)&1 consumed

        // ---- prefetch tile t+1 into stage (t+1)&1 (overlaps GEMM + epilogue) ----
        if (t + 1 < SSEQ / 128) {
            #pragma unroll
            for (int i = 0; i < 2; i++) {
                int idx = tid + i * NT;
                int r = idx >> 3, c = idx & 7;
                CP16(sk + (uint32_t)(((t + 1) & 1) * KSTAGE + r * PADB + c * 16),
                     gKh + kbase + (size_t)(kt + 128 + r) * DKD + c * 8);
            }
            asm volatile("cp.async.commit_group;" ::: "memory");
        }

        const uint32_t bHi = bBase + (uint32_t)((t & 1) * KSTAGE);

        float acc[8][4];
        #pragma unroll
        for (int n = 0; n < 8; n++)
            #pragma unroll
            for (int j = 0; j < 4; j++) acc[n][j] = 0.0f;

        #pragma unroll
        for (int s = 0; s < 4; s++) {
            uint32_t a0, a1, a2, a3;
            LDSM4(a0, a1, a2, a3, aHi + s * 32);
            #pragma unroll
            for (int p = 0; p < 4; p++) {
                uint32_t b0, b1, b2, b3;
                LDSM4(b0, b1, b2, b3, bHi + (uint32_t)(p * 16 * PADB + s * 32));
                mma_f16(acc[2 * p],     a0, a1, a2, a3, b0, b1);
                mma_f16(acc[2 * p + 1], a0, a1, a2, a3, b2, b3);
            }
        }

        // ---- epilogue: packed mask, write scores, exp sums ----
        uint4 mA = *reinterpret_cast<const uint4*>(mp0 + kt);
        uint4 mB = *reinterpret_cast<const uint4*>(mp8 + kt);
        const uint32_t* wa = reinterpret_cast<const uint32_t*>(&mA);
        const uint32_t* wb = reinterpret_cast<const uint32_t*>(&mB);
        #pragma unroll
        for (int nt = 0; nt < 8; nt++) {
            uint32_t ma = wa[nt >> 1] >> ((nt & 1) * 16);
            uint32_t mb = wb[nt >> 1] >> ((nt & 1) * 16);
            float s0 = (ma & 0xFFu)   ? acc[nt][0] : NEGV;
            float s1 = (ma & 0xFF00u) ? acc[nt][1] : NEGV;
            float s2 = (mb & 0xFFu)   ? acc[nt][2] : NEGV;
            float s3 = (mb & 0xFF00u) ? acc[nt][3] : NEGV;
            sumE0 += __expf(s0) + __expf(s1);
            sumE1 += __expf(s2) + __expf(s3);
            int kc = kt + wk * 64 + nt * 8 + 2 * (lane & 3);
            *reinterpret_cast<float2*>(Sp + (size_t)r0l * SSEQ + kc)       = make_float2(s0, s1);
            *reinterpret_cast<float2*>(Sp + (size_t)(r0l + 8) * SSEQ + kc) = make_float2(s2, s3);
        }
    }

    // ---- row-sum reduce ----
    sumE0 += __shfl_xor_sync(0xFFFFFFFFu, sumE0, 1);
    sumE0 += __shfl_xor_sync(0xFFFFFFFFu, sumE0, 2);
    sumE1 += __shfl_xor_sync(0xFFFFFFFFu, sumE1, 1);
    sumE1 += __shfl_xor_sync(0xFFFFFFFFu, sumE1, 2);
    if ((lane & 3) == 0) {
        sred[wk * 128 + r0l]     = sumE0;
        sred[wk * 128 + r0l + 8] = sumE1;
    }
    __syncthreads();
    if (tid < 128) sinv[tid] = 1.0f / (sred[tid] + sred[128 + tid]);
    __syncthreads();

    // ---- fused attn pass: re-read scores in REVERSE tile order (L2 recency) ----
    for (int tile = SSEQ / 128 - 1; tile >= 0; tile--) {
        #pragma unroll
        for (int j = 0; j < 8; j++) {
            int row = j * 16 + wid;
            int idx = row * 256 + tile * 32 + lane;
            float inv = sinv[row];
            float4 s = reinterpret_cast<const float4*>(Sp)[idx];
            float4 a;
            a.x = __expf(s.x) * inv;
            a.y = __expf(s.y) * inv;
            a.z = __expf(s.z) * inv;
            a.w = __expf(s.w) * inv;
            reinterpret_cast<float4*>(Ap)[idx] = a;
        }
    }
}

extern "C" void kernel_launch(void* const* d_in, const int* in_sizes, int n_in,
                              void* d_out, int out_size)
{
    const float* Q = (const float*)d_in[0];
    const float* K = (const float*)d_in[1];
    const int*   M = (const int*)d_in[3];    // d_in[2] = value, unused by outputs

    float* attn   = (float*)d_out;
    float* scores = (float*)d_out + (size_t)BB * HH * SSEQ * SSEQ;

    prep_kernel<<<CVT_BLOCKS + MSK_BLOCKS, 256>>>(Q, K, M);

    cudaFuncSetAttribute(mha_fused, cudaFuncAttributeMaxDynamicSharedMemorySize, SMEM_TOTAL);
    dim3 grid(SSEQ / TQ, HH, BB);            // (8,16,4) = 512 CTAs
    mha_fused<<<grid, NT, SMEM_TOTAL>>>(attn, scores);
}

// round 15
// speedup vs baseline: 1.5907x; 1.0606x over previous
#include <cuda_runtime.h>
#include <cuda_bf16.h>
#include <cuda_fp16.h>
#include <math.h>
#include <stdint.h>

#define BB 4
#define HH 16
#define SSEQ 1024
#define DKD 64
#define TQ 128
#define NT 512
#define NEGV (-1.0e9f)
#define PADB 144

#define KSTAGE  18432                              // one fp16 K tile (128 rows x 144B)
#define OFF_K   18432                              // after Q tile
#define OFF_RED (OFF_K + 2 * KSTAGE)               // 55296
#define SMEM_TOTAL (OFF_RED + (256 + 128) * 4)     // 56832 -> 2+ CTAs/SM

#define NELEM (BB * HH * SSEQ * DKD)
#define NMASK (BB * SSEQ * SSEQ)
#define CVT_BLOCKS ((2 * NELEM / 4) / 256)
#define MSK_BLOCKS ((NMASK / 16) / 256)

__device__ __half gQh[NELEM];
__device__ __half gKh[NELEM];
__device__ __align__(16) uint8_t gMB[NMASK];

__device__ __forceinline__ uint32_t smem_u32(const void* p) {
    uint32_t a;
    asm("{ .reg .u64 t; cvta.to.shared.u64 t, %1; cvt.u32.u64 %0, t; }" : "=r"(a) : "l"(p));
    return a;
}
__device__ __forceinline__ uint32_t pack_h2(float a, float b) {
    __half2 h = __floats2half2_rn(a, b);
    return *reinterpret_cast<uint32_t*>(&h);
}
__device__ __forceinline__ void mma_f16(float* d,
                                        uint32_t a0, uint32_t a1, uint32_t a2, uint32_t a3,
                                        uint32_t b0, uint32_t b1) {
    asm volatile(
        "mma.sync.aligned.m16n8k16.row.col.f32.f16.f16.f32 "
        "{%0,%1,%2,%3}, {%4,%5,%6,%7}, {%8,%9}, {%0,%1,%2,%3};"
        : "+f"(d[0]), "+f"(d[1]), "+f"(d[2]), "+f"(d[3])
        : "r"(a0), "r"(a1), "r"(a2), "r"(a3), "r"(b0), "r"(b1));
}
#define LDSM4(r0, r1, r2, r3, a) \
    asm volatile("ldmatrix.sync.aligned.m8n8.x4.shared.b16 {%0,%1,%2,%3}, [%4];" \
                 : "=r"(r0), "=r"(r1), "=r"(r2), "=r"(r3) : "r"(a))
#define CP16(dst, src) \
    asm volatile("cp.async.cg.shared.global [%0], [%1], 16;" :: "r"(dst), "l"(src) : "memory")

// ---- combined pre-pass: fp16 conversion (Q pre-scaled) + mask byte-packing ----
__global__ void __launch_bounds__(256, 8)
prep_kernel(const float* __restrict__ Q, const float* __restrict__ K,
            const int* __restrict__ M)
{
    if (blockIdx.x < CVT_BLOCKS) {
        size_t i = (size_t)blockIdx.x * 256 + threadIdx.x;
        bool isQ = i < (NELEM / 4);
        size_t j = isQ ? i : i - (NELEM / 4);
        float4 v = reinterpret_cast<const float4*>(isQ ? Q : K)[j];
        if (isQ) { v.x *= 0.125f; v.y *= 0.125f; v.z *= 0.125f; v.w *= 0.125f; }
        uint2 out = make_uint2(pack_h2(v.x, v.y), pack_h2(v.z, v.w));
        reinterpret_cast<uint2*>(isQ ? gQh : gKh)[j] = out;
    } else {
        int t = (blockIdx.x - CVT_BLOCKS) * 256 + threadIdx.x;
        int tile = t >> 3;
        int w = t & 7;
        int half = w >> 2, e = w & 3;
        const int* src = M + (size_t)tile * 128 + half * 64 + 2 * e;
        uint32_t words[4];
        #pragma unroll
        for (int p = 0; p < 4; p++) {
            int2 v0 = *reinterpret_cast<const int2*>(src + (2 * p) * 8);
            int2 v1 = *reinterpret_cast<const int2*>(src + (2 * p + 1) * 8);
            words[p] = (v0.x ? 1u : 0u) | (v0.y ? 0x100u : 0u)
                     | (v1.x ? 0x10000u : 0u) | (v1.y ? 0x1000000u : 0u);
        }
        *reinterpret_cast<uint4*>(gMB + (size_t)tile * 128 + w * 16) =
            make_uint4(words[0], words[1], words[2], words[3]);
    }
}

__global__ void __launch_bounds__(NT, 2)
mha_fused(float* __restrict__ attn, float* __restrict__ scores)
{
    extern __shared__ char sm[];
    float* sred = (float*)(sm + OFF_RED);   // [256]
    float* sinv = sred + 256;               // [128]

    const int tid  = threadIdx.x;
    const int lane = tid & 31;
    const int wid  = tid >> 5;              // 0..15
    const int wq   = wid >> 1;              // 0..7
    const int wk   = wid & 1;               // 0..1
    const int qt = blockIdx.x, h = blockIdx.y, b = blockIdx.z;
    const int q0 = qt * TQ;

    const size_t qbase = ((size_t)(b * HH + h) * SSEQ + q0) * DKD;
    const size_t kbase = (size_t)(b * HH + h) * SSEQ * DKD;
    const uint8_t* Mb = gMB + ((size_t)b * SSEQ + q0) * SSEQ;
    float* Sp = scores + ((size_t)(b * HH + h) * SSEQ + q0) * SSEQ;
    float* Ap = attn   + ((size_t)(b * HH + h) * SSEQ + q0) * SSEQ;

    const uint32_t sq = smem_u32(sm);
    const uint32_t sk = sq + OFF_K;

    // ---- prologue: one group = Q tile + K tile 0 -> stage 0 ----
    #pragma unroll
    for (int i = 0; i < 2; i++) {
        int idx = tid + i * NT;
        int r = idx >> 3, c = idx & 7;
        CP16(sq + (uint32_t)(r * PADB + c * 16), gQh + qbase + (size_t)r * DKD + c * 8);
    }
    #pragma unroll
    for (int i = 0; i < 2; i++) {
        int idx = tid + i * NT;
        int r = idx >> 3, c = idx & 7;
        CP16(sk + (uint32_t)(r * PADB + c * 16), gKh + kbase + (size_t)r * DKD + c * 8);
    }
    asm volatile("cp.async.commit_group;" ::: "memory");

    const uint32_t aHi = sq + (uint32_t)((wq * 16 + (lane & 15)) * PADB + (lane >> 4) * 16);
    const int rowB = wk * 64 + (lane & 7) + (lane >> 4) * 8;
    const uint32_t bBase = sk + (uint32_t)(rowB * PADB + ((lane >> 3) & 1) * 16);

    const int r0l = wq * 16 + (lane >> 2);
    const uint8_t* mp0 = Mb + (size_t)r0l * SSEQ + wk * 64 + (lane & 3) * 16;
    const uint8_t* mp8 = mp0 + 8 * SSEQ;
    float sumE0 = 0.0f, sumE1 = 0.0f;

    // ================= PASS A: sums only (loop identical to R13) =================
    for (int t = 0; t < SSEQ / 128; t++) {
        const int kt = t * 128;
        asm volatile("cp.async.wait_group 0;" ::: "memory");
        __syncthreads();   // tile t resident in stage t&1; other stage consumed

        if (t + 1 < SSEQ / 128) {
            #pragma unroll
            for (int i = 0; i < 2; i++) {
                int idx = tid + i * NT;
                int r = idx >> 3, c = idx & 7;
                CP16(sk + (uint32_t)(((t + 1) & 1) * KSTAGE + r * PADB + c * 16),
                     gKh + kbase + (size_t)(kt + 128 + r) * DKD + c * 8);
            }
            asm volatile("cp.async.commit_group;" ::: "memory");
        }

        const uint32_t bHi = bBase + (uint32_t)((t & 1) * KSTAGE);

        float acc[8][4];
        #pragma unroll
        for (int n = 0; n < 8; n++)
            #pragma unroll
            for (int j = 0; j < 4; j++) acc[n][j] = 0.0f;

        #pragma unroll
        for (int s = 0; s < 4; s++) {
            uint32_t a0, a1, a2, a3;
            LDSM4(a0, a1, a2, a3, aHi + s * 32);
            #pragma unroll
            for (int p = 0; p < 4; p++) {
                uint32_t b0, b1, b2, b3;
                LDSM4(b0, b1, b2, b3, bHi + (uint32_t)(p * 16 * PADB + s * 32));
                mma_f16(acc[2 * p],     a0, a1, a2, a3, b0, b1);
                mma_f16(acc[2 * p + 1], a0, a1, a2, a3, b2, b3);
            }
        }

        uint4 mA = *reinterpret_cast<const uint4*>(mp0 + kt);
        uint4 mB = *reinterpret_cast<const uint4*>(mp8 + kt);
        const uint32_t* wa = reinterpret_cast<const uint32_t*>(&mA);
        const uint32_t* wb = reinterpret_cast<const uint32_t*>(&mB);
        #pragma unroll
        for (int nt = 0; nt < 8; nt++) {
            uint32_t ma = wa[nt >> 1] >> ((nt & 1) * 16);
            uint32_t mb = wb[nt >> 1] >> ((nt & 1) * 16);
            float s0 = (ma & 0xFFu)   ? acc[nt][0] : NEGV;
            float s1 = (ma & 0xFF00u) ? acc[nt][1] : NEGV;
            float s2 = (mb & 0xFFu)   ? acc[nt][2] : NEGV;
            float s3 = (mb & 0xFF00u) ? acc[nt][3] : NEGV;
            sumE0 += __expf(s0) + __expf(s1);
            sumE1 += __expf(s2) + __expf(s3);
        }
    }

    // ---- row-sum reduce -> inv ----
    sumE0 += __shfl_xor_sync(0xFFFFFFFFu, sumE0, 1);
    sumE0 += __shfl_xor_sync(0xFFFFFFFFu, sumE0, 2);
    sumE1 += __shfl_xor_sync(0xFFFFFFFFu, sumE1, 1);
    sumE1 += __shfl_xor_sync(0xFFFFFFFFu, sumE1, 2);
    if ((lane & 3) == 0) {
        sred[wk * 128 + r0l]     = sumE0;
        sred[wk * 128 + r0l + 8] = sumE1;
    }
    __syncthreads();
    if (tid < 128) sinv[tid] = 1.0f / (sred[tid] + sred[128 + tid]);
    __syncthreads();
    const float inv0 = sinv[r0l];
    const float inv8 = sinv[r0l + 8];
    __syncthreads();   // all reads of sinv done before pass B (paranoia; sred reused never)

    // ---- explicit re-prime (R10 style): K tile 0 -> stage 0 ----
    #pragma unroll
    for (int i = 0; i < 2; i++) {
        int idx = tid + i * NT;
        int r = idx >> 3, c = idx & 7;
        CP16(sk + (uint32_t)(r * PADB + c * 16), gKh + kbase + (size_t)r * DKD + c * 8);
    }
    asm volatile("cp.async.commit_group;" ::: "memory");

    // ================= PASS B: recompute, write scores + attn =================
    for (int t = 0; t < SSEQ / 128; t++) {
        const int kt = t * 128;
        asm volatile("cp.async.wait_group 0;" ::: "memory");
        __syncthreads();

        if (t + 1 < SSEQ / 128) {
            #pragma unroll
            for (int i = 0; i < 2; i++) {
                int idx = tid + i * NT;
                int r = idx >> 3, c = idx & 7;
                CP16(sk + (uint32_t)(((t + 1) & 1) * KSTAGE + r * PADB + c * 16),
                     gKh + kbase + (size_t)(kt + 128 + r) * DKD + c * 8);
            }
            asm volatile("cp.async.commit_group;" ::: "memory");
        }

        const uint32_t bHi = bBase + (uint32_t)((t & 1) * KSTAGE);

        float acc[8][4];
        #pragma unroll
        for (int n = 0; n < 8; n++)
            #pragma unroll
            for (int j = 0; j < 4; j++) acc[n][j] = 0.0f;

        #pragma unroll
        for (int s = 0; s < 4; s++) {
            uint32_t a0, a1, a2, a3;
            LDSM4(a0, a1, a2, a3, aHi + s * 32);
            #pragma unroll
            for (int p = 0; p < 4; p++) {
                uint32_t b0, b1, b2, b3;
                LDSM4(b0, b1, b2, b3, bHi + (uint32_t)(p * 16 * PADB + s * 32));
                mma_f16(acc[2 * p],     a0, a1, a2, a3, b0, b1);
                mma_f16(acc[2 * p + 1], a0, a1, a2, a3, b2, b3);
            }
        }

        uint4 mA = *reinterpret_cast<const uint4*>(mp0 + kt);
        uint4 mB = *reinterpret_cast<const uint4*>(mp8 + kt);
        const uint32_t* wa = reinterpret_cast<const uint32_t*>(&mA);
        const uint32_t* wb = reinterpret_cast<const uint32_t*>(&mB);
        #pragma unroll
        for (int nt = 0; nt < 8; nt++) {
            uint32_t ma = wa[nt >> 1] >> ((nt & 1) * 16);
            uint32_t mb = wb[nt >> 1] >> ((nt & 1) * 16);
            float s0 = (ma & 0xFFu)   ? acc[nt][0] : NEGV;
            float s1 = (ma & 0xFF00u) ? acc[nt][1] : NEGV;
            float s2 = (mb & 0xFFu)   ? acc[nt][2] : NEGV;
            float s3 = (mb & 0xFF00u) ? acc[nt][3] : NEGV;
            int kc = kt + wk * 64 + nt * 8 + 2 * (lane & 3);
            *reinterpret_cast<float2*>(Sp + (size_t)r0l * SSEQ + kc) =
                make_float2(s0, s1);
            *reinterpret_cast<float2*>(Sp + (size_t)(r0l + 8) * SSEQ + kc) =
                make_float2(s2, s3);
            *reinterpret_cast<float2*>(Ap + (size_t)r0l * SSEQ + kc) =
                make_float2(__expf(s0) * inv0, __expf(s1) * inv0);
            *reinterpret_cast<float2*>(Ap + (size_t)(r0l + 8) * SSEQ + kc) =
                make_float2(__expf(s2) * inv8, __expf(s3) * inv8);
        }
    }
}

extern "C" void kernel_launch(void* const* d_in, const int* in_sizes, int n_in,
                              void* d_out, int out_size)
{
    const float* Q = (const float*)d_in[0];
    const float* K = (const float*)d_in[1];
    const int*   M = (const int*)d_in[3];    // d_in[2] = value, unused by outputs

    float* attn   = (float*)d_out;
    float* scores = (float*)d_out + (size_t)BB * HH * SSEQ * SSEQ;

    prep_kernel<<<CVT_BLOCKS + MSK_BLOCKS, 256>>>(Q, K, M);

    cudaFuncSetAttribute(mha_fused, cudaFuncAttributeMaxDynamicSharedMemorySize, SMEM_TOTAL);
    dim3 grid(SSEQ / TQ, HH, BB);            // (8,16,4) = 512 CTAs
    mha_fused<<<grid, NT, SMEM_TOTAL>>>(attn, scores);
}

// round 16
// speedup vs baseline: 1.6510x; 1.0379x over previous
#include <cuda_runtime.h>
#include <cuda_bf16.h>
#include <cuda_fp16.h>
#include <math.h>
#include <stdint.h>

#define BB 4
#define HH 16
#define SSEQ 1024
#define DKD 64
#define TQ 128
#define NT 256
#define NEGV (-1.0e9f)
#define PADB 144

#define KSTAGE  18432
#define OFF_K   18432
#define OFF_RED (OFF_K + 2 * KSTAGE)               // 55296
#define SMEM_TOTAL (OFF_RED + (256 + 128) * 4)     // 56832 -> 2 CTAs/SM

#define NELEM (BB * HH * SSEQ * DKD)
#define NMASK (BB * SSEQ * SSEQ)
#define CVT_BLOCKS ((2 * NELEM / 4) / 256)
#define MSK_BLOCKS ((NMASK / 16) / 256)

__device__ __half gQh[NELEM];
__device__ __half gKh[NELEM];
__device__ __align__(16) uint8_t gMB[NMASK];

__device__ __forceinline__ uint32_t smem_u32(const void* p) {
    uint32_t a;
    asm("{ .reg .u64 t; cvta.to.shared.u64 t, %1; cvt.u32.u64 %0, t; }" : "=r"(a) : "l"(p));
    return a;
}
__device__ __forceinline__ uint32_t pack_h2(float a, float b) {
    __half2 h = __floats2half2_rn(a, b);
    return *reinterpret_cast<uint32_t*>(&h);
}
__device__ __forceinline__ void mma_f16(float* d,
                                        uint32_t a0, uint32_t a1, uint32_t a2, uint32_t a3,
                                        uint32_t b0, uint32_t b1) {
    asm volatile(
        "mma.sync.aligned.m16n8k16.row.col.f32.f16.f16.f32 "
        "{%0,%1,%2,%3}, {%4,%5,%6,%7}, {%8,%9}, {%0,%1,%2,%3};"
        : "+f"(d[0]), "+f"(d[1]), "+f"(d[2]), "+f"(d[3])
        : "r"(a0), "r"(a1), "r"(a2), "r"(a3), "r"(b0), "r"(b1));
}
#define LDSM4(r0, r1, r2, r3, a) \
    asm volatile("ldmatrix.sync.aligned.m8n8.x4.shared.b16 {%0,%1,%2,%3}, [%4];" \
                 : "=r"(r0), "=r"(r1), "=r"(r2), "=r"(r3) : "r"(a))
#define CP16(dst, src) \
    asm volatile("cp.async.cg.shared.global [%0], [%1], 16;" :: "r"(dst), "l"(src) : "memory")

// ---- combined pre-pass: fp16 conversion (Q pre-scaled) + mask byte-packing ----
__global__ void __launch_bounds__(256, 8)
prep_kernel(const float* __restrict__ Q, const float* __restrict__ K,
            const int* __restrict__ M)
{
    if (blockIdx.x < CVT_BLOCKS) {
        size_t i = (size_t)blockIdx.x * 256 + threadIdx.x;
        bool isQ = i < (NELEM / 4);
        size_t j = isQ ? i : i - (NELEM / 4);
        float4 v = reinterpret_cast<const float4*>(isQ ? Q : K)[j];
        if (isQ) { v.x *= 0.125f; v.y *= 0.125f; v.z *= 0.125f; v.w *= 0.125f; }
        uint2 out = make_uint2(pack_h2(v.x, v.y), pack_h2(v.z, v.w));
        reinterpret_cast<uint2*>(isQ ? gQh : gKh)[j] = out;
    } else {
        int t = (blockIdx.x - CVT_BLOCKS) * 256 + threadIdx.x;
        int tile = t >> 3;
        int w = t & 7;
        int half = w >> 2, e = w & 3;
        const int* src = M + (size_t)tile * 128 + half * 64 + 2 * e;
        uint32_t words[4];
        #pragma unroll
        for (int p = 0; p < 4; p++) {
            int2 v0 = *reinterpret_cast<const int2*>(src + (2 * p) * 8);
            int2 v1 = *reinterpret_cast<const int2*>(src + (2 * p + 1) * 8);
            words[p] = (v0.x ? 1u : 0u) | (v0.y ? 0x100u : 0u)
                     | (v1.x ? 0x10000u : 0u) | (v1.y ? 0x1000000u : 0u);
        }
        *reinterpret_cast<uint4*>(gMB + (size_t)tile * 128 + w * 16) =
            make_uint4(words[0], words[1], words[2], words[3]);
    }
}

__global__ void __launch_bounds__(NT, 2)
mha_fused(float* __restrict__ attn, float* __restrict__ scores)
{
    extern __shared__ char sm[];
    float* sred = (float*)(sm + OFF_RED);   // [256]
    float* sinv = sred + 256;               // [128]

    const int tid  = threadIdx.x;
    const int lane = tid & 31;
    const int wid  = tid >> 5;              // 0..7
    const int wq   = wid >> 1;              // 0..3 : 32-row q subtile
    const int wk   = wid & 1;               // 0..1 : 64-col k half
    const int qt = blockIdx.x, h = blockIdx.y, b = blockIdx.z;
    const int q0 = qt * TQ;

    const size_t qbase = ((size_t)(b * HH + h) * SSEQ + q0) * DKD;
    const size_t kbase = (size_t)(b * HH + h) * SSEQ * DKD;
    const uint8_t* Mb = gMB + ((size_t)b * SSEQ + q0) * SSEQ;
    float* Sp = scores + ((size_t)(b * HH + h) * SSEQ + q0) * SSEQ;
    float* Ap = attn   + ((size_t)(b * HH + h) * SSEQ + q0) * SSEQ;

    const uint32_t sq = smem_u32(sm);
    const uint32_t sk = sq + OFF_K;

    // ---- prologue: Q tile + K tile 0 -> stage 0 (1024 chunks each, 4 iters) ----
    #pragma unroll
    for (int i = 0; i < 4; i++) {
        int idx = tid + i * NT;
        int r = idx >> 3, c = idx & 7;
        CP16(sq + (uint32_t)(r * PADB + c * 16), gQh + qbase + (size_t)r * DKD + c * 8);
    }
    #pragma unroll
    for (int i = 0; i < 4; i++) {
        int idx = tid + i * NT;
        int r = idx >> 3, c = idx & 7;
        CP16(sk + (uint32_t)(r * PADB + c * 16), gKh + kbase + (size_t)r * DKD + c * 8);
    }
    asm volatile("cp.async.commit_group;" ::: "memory");

    // A fragment addresses for the two 16-row subsets
    const uint32_t aHi0 = sq + (uint32_t)((wq * 32 + (lane & 15)) * PADB + (lane >> 4) * 16);
    const uint32_t aHi1 = aHi0 + 16 * PADB;
    const int rowB = wk * 64 + (lane & 7) + (lane >> 4) * 8;
    const uint32_t bBase = sk + (uint32_t)(rowB * PADB + ((lane >> 3) & 1) * 16);

    const int r0l = wq * 32 + (lane >> 2);   // rows r0l, +8, +16, +24
    const uint8_t* mpr = Mb + (size_t)r0l * SSEQ + wk * 64 + (lane & 3) * 16;
    float sumE[4] = {0.0f, 0.0f, 0.0f, 0.0f};
    float invr[4];

    // ================= PASS A: sums only =================
    for (int t = 0; t < SSEQ / 128; t++) {
        const int kt = t * 128;
        asm volatile("cp.async.wait_group 0;" ::: "memory");
        __syncthreads();

        if (t + 1 < SSEQ / 128) {
            #pragma unroll
            for (int i = 0; i < 4; i++) {
                int idx = tid + i * NT;
                int r = idx >> 3, c = idx & 7;
                CP16(sk + (uint32_t)(((t + 1) & 1) * KSTAGE + r * PADB + c * 16),
                     gKh + kbase + (size_t)(kt + 128 + r) * DKD + c * 8);
            }
            asm volatile("cp.async.commit_group;" ::: "memory");
        }

        const uint32_t bHi = bBase + (uint32_t)((t & 1) * KSTAGE);

        float acc[2][8][4];
        #pragma unroll
        for (int rr = 0; rr < 2; rr++)
            #pragma unroll
            for (int n = 0; n < 8; n++)
                #pragma unroll
                for (int j = 0; j < 4; j++) acc[rr][n][j] = 0.0f;

        #pragma unroll
        for (int s = 0; s < 4; s++) {
            uint32_t a0, a1, a2, a3, a4, a5, a6, a7;
            LDSM4(a0, a1, a2, a3, aHi0 + s * 32);
            LDSM4(a4, a5, a6, a7, aHi1 + s * 32);
            #pragma unroll
            for (int p = 0; p < 4; p++) {
                uint32_t b0, b1, b2, b3;
                LDSM4(b0, b1, b2, b3, bHi + (uint32_t)(p * 16 * PADB + s * 32));
                mma_f16(acc[0][2 * p],     a0, a1, a2, a3, b0, b1);
                mma_f16(acc[0][2 * p + 1], a0, a1, a2, a3, b2, b3);
                mma_f16(acc[1][2 * p],     a4, a5, a6, a7, b0, b1);
                mma_f16(acc[1][2 * p + 1], a4, a5, a6, a7, b2, b3);
            }
        }

        // ---- epilogue: packed masks (4 row-groups), exp sums ----
        #pragma unroll
        for (int rr = 0; rr < 2; rr++) {
            uint4 mA = *reinterpret_cast<const uint4*>(mpr + (size_t)(rr * 16) * SSEQ + kt);
            uint4 mB = *reinterpret_cast<const uint4*>(mpr + (size_t)(rr * 16 + 8) * SSEQ + kt);
            const uint32_t* wa = reinterpret_cast<const uint32_t*>(&mA);
            const uint32_t* wb = reinterpret_cast<const uint32_t*>(&mB);
            #pragma unroll
            for (int nt = 0; nt < 8; nt++) {
                uint32_t ma = wa[nt >> 1] >> ((nt & 1) * 16);
                uint32_t mb = wb[nt >> 1] >> ((nt & 1) * 16);
                float s0 = (ma & 0xFFu)   ? acc[rr][nt][0] : NEGV;
                float s1 = (ma & 0xFF00u) ? acc[rr][nt][1] : NEGV;
                float s2 = (mb & 0xFFu)   ? acc[rr][nt][2] : NEGV;
                float s3 = (mb & 0xFF00u) ? acc[rr][nt][3] : NEGV;
                sumE[2 * rr]     += __expf(s0) + __expf(s1);
                sumE[2 * rr + 1] += __expf(s2) + __expf(s3);
            }
        }
    }

    // ---- row-sum reduce -> inv ----
    #pragma unroll
    for (int r = 0; r < 4; r++) {
        sumE[r] += __shfl_xor_sync(0xFFFFFFFFu, sumE[r], 1);
        sumE[r] += __shfl_xor_sync(0xFFFFFFFFu, sumE[r], 2);
    }
    if ((lane & 3) == 0) {
        sred[wk * 128 + r0l]      = sumE[0];
        sred[wk * 128 + r0l + 8]  = sumE[1];
        sred[wk * 128 + r0l + 16] = sumE[2];
        sred[wk * 128 + r0l + 24] = sumE[3];
    }
    __syncthreads();
    if (tid < 128) sinv[tid] = 1.0f / (sred[tid] + sred[128 + tid]);
    __syncthreads();
    invr[0] = sinv[r0l];
    invr[1] = sinv[r0l + 8];
    invr[2] = sinv[r0l + 16];
    invr[3] = sinv[r0l + 24];

    // ---- explicit re-prime: K tile 0 -> stage 0 ----
    #pragma unroll
    for (int i = 0; i < 4; i++) {
        int idx = tid + i * NT;
        int r = idx >> 3, c = idx & 7;
        CP16(sk + (uint32_t)(r * PADB + c * 16), gKh + kbase + (size_t)r * DKD + c * 8);
    }
    asm volatile("cp.async.commit_group;" ::: "memory");

    // ================= PASS B: recompute, write scores + attn =================
    for (int t = 0; t < SSEQ / 128; t++) {
        const int kt = t * 128;
        asm volatile("cp.async.wait_group 0;" ::: "memory");
        __syncthreads();

        if (t + 1 < SSEQ / 128) {
            #pragma unroll
            for (int i = 0; i < 4; i++) {
                int idx = tid + i * NT;
                int r = idx >> 3, c = idx & 7;
                CP16(sk + (uint32_t)(((t + 1) & 1) * KSTAGE + r * PADB + c * 16),
                     gKh + kbase + (size_t)(kt + 128 + r) * DKD + c * 8);
            }
            asm volatile("cp.async.commit_group;" ::: "memory");
        }

        const uint32_t bHi = bBase + (uint32_t)((t & 1) * KSTAGE);

        float acc[2][8][4];
        #pragma unroll
        for (int rr = 0; rr < 2; rr++)
            #pragma unroll
            for (int n = 0; n < 8; n++)
                #pragma unroll
                for (int j = 0; j < 4; j++) acc[rr][n][j] = 0.0f;

        #pragma unroll
        for (int s = 0; s < 4; s++) {
            uint32_t a0, a1, a2, a3, a4, a5, a6, a7;
            LDSM4(a0, a1, a2, a3, aHi0 + s * 32);
            LDSM4(a4, a5, a6, a7, aHi1 + s * 32);
            #pragma unroll
            for (int p = 0; p < 4; p++) {
                uint32_t b0, b1, b2, b3;
                LDSM4(b0, b1, b2, b3, bHi + (uint32_t)(p * 16 * PADB + s * 32));
                mma_f16(acc[0][2 * p],     a0, a1, a2, a3, b0, b1);
                mma_f16(acc[0][2 * p + 1], a0, a1, a2, a3, b2, b3);
                mma_f16(acc[1][2 * p],     a4, a5, a6, a7, b0, b1);
                mma_f16(acc[1][2 * p + 1], a4, a5, a6, a7, b2, b3);
            }
        }

        #pragma unroll
        for (int rr = 0; rr < 2; rr++) {
            uint4 mA = *reinterpret_cast<const uint4*>(mpr + (size_t)(rr * 16) * SSEQ + kt);
            uint4 mB = *reinterpret_cast<const uint4*>(mpr + (size_t)(rr * 16 + 8) * SSEQ + kt);
            const uint32_t* wa = reinterpret_cast<const uint32_t*>(&mA);
            const uint32_t* wb = reinterpret_cast<const uint32_t*>(&mB);
            const float iv0 = invr[2 * rr], iv1 = invr[2 * rr + 1];
            const int ra = r0l + rr * 16, rb = ra + 8;
            #pragma unroll
            for (int nt = 0; nt < 8; nt++) {
                uint32_t ma = wa[nt >> 1] >> ((nt & 1) * 16);
                uint32_t mb = wb[nt >> 1] >> ((nt & 1) * 16);
                float s0 = (ma & 0xFFu)   ? acc[rr][nt][0] : NEGV;
                float s1 = (ma & 0xFF00u) ? acc[rr][nt][1] : NEGV;
                float s2 = (mb & 0xFFu)   ? acc[rr][nt][2] : NEGV;
                float s3 = (mb & 0xFF00u) ? acc[rr][nt][3] : NEGV;
                int kc = kt + wk * 64 + nt * 8 + 2 * (lane & 3);
                *reinterpret_cast<float2*>(Sp + (size_t)ra * SSEQ + kc) = make_float2(s0, s1);
                *reinterpret_cast<float2*>(Sp + (size_t)rb * SSEQ + kc) = make_float2(s2, s3);
                *reinterpret_cast<float2*>(Ap + (size_t)ra * SSEQ + kc) =
                    make_float2(__expf(s0) * iv0, __expf(s1) * iv0);
                *reinterpret_cast<float2*>(Ap + (size_t)rb * SSEQ + kc) =
                    make_float2(__expf(s2) * iv1, __expf(s3) * iv1);
            }
        }
    }
}

extern "C" void kernel_launch(void* const* d_in, const int* in_sizes, int n_in,
                              void* d_out, int out_size)
{
    const float* Q = (const float*)d_in[0];
    const float* K = (const float*)d_in[1];
    const int*   M = (const int*)d_in[3];    // d_in[2] = value, unused by outputs

    float* attn   = (float*)d_out;
    float* scores = (float*)d_out + (size_t)BB * HH * SSEQ * SSEQ;

    prep_kernel<<<CVT_BLOCKS + MSK_BLOCKS, 256>>>(Q, K, M);

    cudaFuncSetAttribute(mha_fused, cudaFuncAttributeMaxDynamicSharedMemorySize, SMEM_TOTAL);
    dim3 grid(SSEQ / TQ, HH, BB);            // (8,16,4) = 512 CTAs
    mha_fused<<<grid, NT, SMEM_TOTAL>>>(attn, scores);
}

// round 17
// speedup vs baseline: 1.7033x; 1.0316x over previous
#include <cuda_runtime.h>
#include <cuda_bf16.h>
#include <cuda_fp16.h>
#include <math.h>
#include <stdint.h>

#define BB 4
#define HH 16
#define SSEQ 1024
#define DKD 64
#define TQ 128
#define NT 256
#define NEGV (-1.0e9f)
#define PADB 144

#define KSTAGE  18432
#define OFF_K   18432
#define OFF_RED (OFF_K + 2 * KSTAGE)               // 55296
#define OFF_STG (OFF_RED + (256 + 128) * 4)        // 56832
#define STGW    272                                 // staging row stride (17*16B)
#define WSTG    (16 * STGW)                         // 4352 per warp
#define SMEM_TOTAL (OFF_STG + 8 * WSTG)             // 91648 -> still 2 CTAs/SM

#define NELEM (BB * HH * SSEQ * DKD)
#define NMASK (BB * SSEQ * SSEQ)
#define CVT_BLOCKS ((2 * NELEM / 4) / 256)
#define MSK_BLOCKS ((NMASK / 16) / 256)

__device__ __half gQh[NELEM];
__device__ __half gKh[NELEM];
__device__ __align__(16) uint8_t gMB[NMASK];

__device__ __forceinline__ uint32_t smem_u32(const void* p) {
    uint32_t a;
    asm("{ .reg .u64 t; cvta.to.shared.u64 t, %1; cvt.u32.u64 %0, t; }" : "=r"(a) : "l"(p));
    return a;
}
__device__ __forceinline__ uint32_t pack_h2(float a, float b) {
    __half2 h = __floats2half2_rn(a, b);
    return *reinterpret_cast<uint32_t*>(&h);
}
__device__ __forceinline__ void mma_f16(float* d,
                                        uint32_t a0, uint32_t a1, uint32_t a2, uint32_t a3,
                                        uint32_t b0, uint32_t b1) {
    asm volatile(
        "mma.sync.aligned.m16n8k16.row.col.f32.f16.f16.f32 "
        "{%0,%1,%2,%3}, {%4,%5,%6,%7}, {%8,%9}, {%0,%1,%2,%3};"
        : "+f"(d[0]), "+f"(d[1]), "+f"(d[2]), "+f"(d[3])
        : "r"(a0), "r"(a1), "r"(a2), "r"(a3), "r"(b0), "r"(b1));
}
#define LDSM4(r0, r1, r2, r3, a) \
    asm volatile("ldmatrix.sync.aligned.m8n8.x4.shared.b16 {%0,%1,%2,%3}, [%4];" \
                 : "=r"(r0), "=r"(r1), "=r"(r2), "=r"(r3) : "r"(a))
#define CP16(dst, src) \
    asm volatile("cp.async.cg.shared.global [%0], [%1], 16;" :: "r"(dst), "l"(src) : "memory")

// ---- combined pre-pass: fp16 conversion (Q pre-scaled) + mask byte-packing ----
__global__ void __launch_bounds__(256, 8)
prep_kernel(const float* __restrict__ Q, const float* __restrict__ K,
            const int* __restrict__ M)
{
    if (blockIdx.x < CVT_BLOCKS) {
        size_t i = (size_t)blockIdx.x * 256 + threadIdx.x;
        bool isQ = i < (NELEM / 4);
        size_t j = isQ ? i : i - (NELEM / 4);
        float4 v = reinterpret_cast<const float4*>(isQ ? Q : K)[j];
        if (isQ) { v.x *= 0.125f; v.y *= 0.125f; v.z *= 0.125f; v.w *= 0.125f; }
        uint2 out = make_uint2(pack_h2(v.x, v.y), pack_h2(v.z, v.w));
        reinterpret_cast<uint2*>(isQ ? gQh : gKh)[j] = out;
    } else {
        int t = (blockIdx.x - CVT_BLOCKS) * 256 + threadIdx.x;
        int tile = t >> 3;
        int w = t & 7;
        int half = w >> 2, e = w & 3;
        const int* src = M + (size_t)tile * 128 + half * 64 + 2 * e;
        uint32_t words[4];
        #pragma unroll
        for (int p = 0; p < 4; p++) {
            int2 v0 = *reinterpret_cast<const int2*>(src + (2 * p) * 8);
            int2 v1 = *reinterpret_cast<const int2*>(src + (2 * p + 1) * 8);
            words[p] = (v0.x ? 1u : 0u) | (v0.y ? 0x100u : 0u)
                     | (v1.x ? 0x10000u : 0u) | (v1.y ? 0x1000000u : 0u);
        }
        *reinterpret_cast<uint4*>(gMB + (size_t)tile * 128 + w * 16) =
            make_uint4(words[0], words[1], words[2], words[3]);
    }
}

__global__ void __launch_bounds__(NT, 2)
mha_fused(float* __restrict__ attn, float* __restrict__ scores)
{
    extern __shared__ char sm[];
    float* sred = (float*)(sm + OFF_RED);   // [256]
    float* sinv = sred + 256;               // [128]

    const int tid  = threadIdx.x;
    const int lane = tid & 31;
    const int wid  = tid >> 5;              // 0..7
    const int wq   = wid >> 1;              // 0..3 : 32-row q subtile
    const int wk   = wid & 1;               // 0..1 : 64-col k half
    const int qt = blockIdx.x, h = blockIdx.y, b = blockIdx.z;
    const int q0 = qt * TQ;

    const size_t qbase = ((size_t)(b * HH + h) * SSEQ + q0) * DKD;
    const size_t kbase = (size_t)(b * HH + h) * SSEQ * DKD;
    const uint8_t* Mb = gMB + ((size_t)b * SSEQ + q0) * SSEQ;
    float* Sp = scores + ((size_t)(b * HH + h) * SSEQ + q0) * SSEQ;
    float* Ap = attn   + ((size_t)(b * HH + h) * SSEQ + q0) * SSEQ;

    const uint32_t sq = smem_u32(sm);
    const uint32_t sk = sq + OFF_K;
    char* stgp = sm + OFF_STG + wid * WSTG;  // per-warp 16x272B staging

    // ---- prologue: Q tile + K tile 0 -> stage 0 ----
    #pragma unroll
    for (int i = 0; i < 4; i++) {
        int idx = tid + i * NT;
        int r = idx >> 3, c = idx & 7;
        CP16(sq + (uint32_t)(r * PADB + c * 16), gQh + qbase + (size_t)r * DKD + c * 8);
    }
    #pragma unroll
    for (int i = 0; i < 4; i++) {
        int idx = tid + i * NT;
        int r = idx >> 3, c = idx & 7;
        CP16(sk + (uint32_t)(r * PADB + c * 16), gKh + kbase + (size_t)r * DKD + c * 8);
    }
    asm volatile("cp.async.commit_group;" ::: "memory");

    const uint32_t aHi0 = sq + (uint32_t)((wq * 32 + (lane & 15)) * PADB + (lane >> 4) * 16);
    const uint32_t aHi1 = aHi0 + 16 * PADB;
    const int rowB = wk * 64 + (lane & 7) + (lane >> 4) * 8;
    const uint32_t bBase = sk + (uint32_t)(rowB * PADB + ((lane >> 3) & 1) * 16);

    const int r0l = wq * 32 + (lane >> 2);
    const uint8_t* mpr = Mb + (size_t)r0l * SSEQ + wk * 64 + (lane & 3) * 16;
    float sumE[4] = {0.0f, 0.0f, 0.0f, 0.0f};

    // ================= PASS A: sums only =================
    for (int t = 0; t < SSEQ / 128; t++) {
        const int kt = t * 128;
        asm volatile("cp.async.wait_group 0;" ::: "memory");
        __syncthreads();

        if (t + 1 < SSEQ / 128) {
            #pragma unroll
            for (int i = 0; i < 4; i++) {
                int idx = tid + i * NT;
                int r = idx >> 3, c = idx & 7;
                CP16(sk + (uint32_t)(((t + 1) & 1) * KSTAGE + r * PADB + c * 16),
                     gKh + kbase + (size_t)(kt + 128 + r) * DKD + c * 8);
            }
            asm volatile("cp.async.commit_group;" ::: "memory");
        }

        const uint32_t bHi = bBase + (uint32_t)((t & 1) * KSTAGE);

        float acc[2][8][4];
        #pragma unroll
        for (int rr = 0; rr < 2; rr++)
            #pragma unroll
            for (int n = 0; n < 8; n++)
                #pragma unroll
                for (int j = 0; j < 4; j++) acc[rr][n][j] = 0.0f;

        #pragma unroll
        for (int s = 0; s < 4; s++) {
            uint32_t a0, a1, a2, a3, a4, a5, a6, a7;
            LDSM4(a0, a1, a2, a3, aHi0 + s * 32);
            LDSM4(a4, a5, a6, a7, aHi1 + s * 32);
            #pragma unroll
            for (int p = 0; p < 4; p++) {
                uint32_t b0, b1, b2, b3;
                LDSM4(b0, b1, b2, b3, bHi + (uint32_t)(p * 16 * PADB + s * 32));
                mma_f16(acc[0][2 * p],     a0, a1, a2, a3, b0, b1);
                mma_f16(acc[0][2 * p + 1], a0, a1, a2, a3, b2, b3);
                mma_f16(acc[1][2 * p],     a4, a5, a6, a7, b0, b1);
                mma_f16(acc[1][2 * p + 1], a4, a5, a6, a7, b2, b3);
            }
        }

        #pragma unroll
        for (int rr = 0; rr < 2; rr++) {
            uint4 mA = *reinterpret_cast<const uint4*>(mpr + (size_t)(rr * 16) * SSEQ + kt);
            uint4 mB = *reinterpret_cast<const uint4*>(mpr + (size_t)(rr * 16 + 8) * SSEQ + kt);
            const uint32_t* wa = reinterpret_cast<const uint32_t*>(&mA);
            const uint32_t* wb = reinterpret_cast<const uint32_t*>(&mB);
            #pragma unroll
            for (int nt = 0; nt < 8; nt++) {
                uint32_t ma = wa[nt >> 1] >> ((nt & 1) * 16);
                uint32_t mb = wb[nt >> 1] >> ((nt & 1) * 16);
                float s0 = (ma & 0xFFu)   ? acc[rr][nt][0] : NEGV;
                float s1 = (ma & 0xFF00u) ? acc[rr][nt][1] : NEGV;
                float s2 = (mb & 0xFFu)   ? acc[rr][nt][2] : NEGV;
                float s3 = (mb & 0xFF00u) ? acc[rr][nt][3] : NEGV;
                sumE[2 * rr]     += __expf(s0) + __expf(s1);
                sumE[2 * rr + 1] += __expf(s2) + __expf(s3);
            }
        }
    }

    // ---- row-sum reduce -> sinv ----
    #pragma unroll
    for (int r = 0; r < 4; r++) {
        sumE[r] += __shfl_xor_sync(0xFFFFFFFFu, sumE[r], 1);
        sumE[r] += __shfl_xor_sync(0xFFFFFFFFu, sumE[r], 2);
    }
    if ((lane & 3) == 0) {
        sred[wk * 128 + r0l]      = sumE[0];
        sred[wk * 128 + r0l + 8]  = sumE[1];
        sred[wk * 128 + r0l + 16] = sumE[2];
        sred[wk * 128 + r0l + 24] = sumE[3];
    }
    __syncthreads();
    if (tid < 128) sinv[tid] = 1.0f / (sred[tid] + sred[128 + tid]);
    __syncthreads();

    // ---- explicit re-prime: K tile 0 -> stage 0 ----
    #pragma unroll
    for (int i = 0; i < 4; i++) {
        int idx = tid + i * NT;
        int r = idx >> 3, c = idx & 7;
        CP16(sk + (uint32_t)(r * PADB + c * 16), gKh + kbase + (size_t)r * DKD + c * 8);
    }
    asm volatile("cp.async.commit_group;" ::: "memory");

    // ================= PASS B: recompute, staged coalesced writes =================
    const int hi16 = lane >> 4, lo16 = lane & 15;
    for (int t = 0; t < SSEQ / 128; t++) {
        const int kt = t * 128;
        asm volatile("cp.async.wait_group 0;" ::: "memory");
        __syncthreads();

        if (t + 1 < SSEQ / 128) {
            #pragma unroll
            for (int i = 0; i < 4; i++) {
                int idx = tid + i * NT;
                int r = idx >> 3, c = idx & 7;
                CP16(sk + (uint32_t)(((t + 1) & 1) * KSTAGE + r * PADB + c * 16),
                     gKh + kbase + (size_t)(kt + 128 + r) * DKD + c * 8);
            }
            asm volatile("cp.async.commit_group;" ::: "memory");
        }

        const uint32_t bHi = bBase + (uint32_t)((t & 1) * KSTAGE);

        float acc[2][8][4];
        #pragma unroll
        for (int rr = 0; rr < 2; rr++)
            #pragma unroll
            for (int n = 0; n < 8; n++)
                #pragma unroll
                for (int j = 0; j < 4; j++) acc[rr][n][j] = 0.0f;

        #pragma unroll
        for (int s = 0; s < 4; s++) {
            uint32_t a0, a1, a2, a3, a4, a5, a6, a7;
            LDSM4(a0, a1, a2, a3, aHi0 + s * 32);
            LDSM4(a4, a5, a6, a7, aHi1 + s * 32);
            #pragma unroll
            for (int p = 0; p < 4; p++) {
                uint32_t b0, b1, b2, b3;
                LDSM4(b0, b1, b2, b3, bHi + (uint32_t)(p * 16 * PADB + s * 32));
                mma_f16(acc[0][2 * p],     a0, a1, a2, a3, b0, b1);
                mma_f16(acc[0][2 * p + 1], a0, a1, a2, a3, b2, b3);
                mma_f16(acc[1][2 * p],     a4, a5, a6, a7, b0, b1);
                mma_f16(acc[1][2 * p + 1], a4, a5, a6, a7, b2, b3);
            }
        }

        #pragma unroll
        for (int rr = 0; rr < 2; rr++) {
            uint4 mA = *reinterpret_cast<const uint4*>(mpr + (size_t)(rr * 16) * SSEQ + kt);
            uint4 mB = *reinterpret_cast<const uint4*>(mpr + (size_t)(rr * 16 + 8) * SSEQ + kt);
            const uint32_t* wa = reinterpret_cast<const uint32_t*>(&mA);
            const uint32_t* wb = reinterpret_cast<const uint32_t*>(&mB);

            // stage masked scores (fragment layout -> row-major staging)
            char* srow0 = stgp + (lane >> 2) * STGW + (lane & 3) * 8;
            #pragma unroll
            for (int nt = 0; nt < 8; nt++) {
                uint32_t ma = wa[nt >> 1] >> ((nt & 1) * 16);
                uint32_t mb = wb[nt >> 1] >> ((nt & 1) * 16);
                float s0 = (ma & 0xFFu)   ? acc[rr][nt][0] : NEGV;
                float s1 = (ma & 0xFF00u) ? acc[rr][nt][1] : NEGV;
                float s2 = (mb & 0xFFu)   ? acc[rr][nt][2] : NEGV;
                float s3 = (mb & 0xFF00u) ? acc[rr][nt][3] : NEGV;
                *reinterpret_cast<float2*>(srow0 + nt * 32)            = make_float2(s0, s1);
                *reinterpret_cast<float2*>(srow0 + 8 * STGW + nt * 32) = make_float2(s2, s3);
            }
            __syncwarp();

            // coalesced emit: 16 rows x 256B; lanes 0-15 = one row chunk
            const int rbase = wq * 32 + rr * 16;
            #pragma unroll
            for (int j = 0; j < 8; j++) {
                int row = 2 * j + hi16;            // local row 0..15
                float4 v = *reinterpret_cast<float4*>(stgp + row * STGW + lo16 * 16);
                float inv = sinv[rbase + row];
                size_t go = (size_t)(rbase + row) * SSEQ + kt + wk * 64 + lo16 * 4;
                *reinterpret_cast<float4*>(Sp + go) = v;
                float4 a;
                a.x = __expf(v.x) * inv;
                a.y = __expf(v.y) * inv;
                a.z = __expf(v.z) * inv;
                a.w = __expf(v.w) * inv;
                *reinterpret_cast<float4*>(Ap + go) = a;
            }
            __syncwarp();
        }
    }
}

extern "C" void kernel_launch(void* const* d_in, const int* in_sizes, int n_in,
                              void* d_out, int out_size)
{
    const float* Q = (const float*)d_in[0];
    const float* K = (const float*)d_in[1];
    const int*   M = (const int*)d_in[3];    // d_in[2] = value, unused by outputs

    float* attn   = (float*)d_out;
    float* scores = (float*)d_out + (size_t)BB * HH * SSEQ * SSEQ;

    prep_kernel<<<CVT_BLOCKS + MSK_BLOCKS, 256>>>(Q, K, M);

    cudaFuncSetAttribute(mha_fused, cudaFuncAttributeMaxDynamicSharedMemorySize, SMEM_TOTAL);
    dim3 grid(SSEQ / TQ, HH, BB);            // (8,16,4) = 512 CTAs
    mha_fused<<<grid, NT, SMEM_TOTAL>>>(attn, scores);
}